// round 1
// baseline (speedup 1.0000x reference)
#include <cuda_runtime.h>
#include <cuda_bf16.h>
#include <cstdint>

// Problem constants
#define TT     16384          // B*T total timesteps
#define FEAT   620
#define NH     128
#define STATE  2176
#define NIN    2796           // FEAT + STATE

// ---------------- scratch (static device globals; no allocation) -------------
__device__ __align__(16) float g_U[(TT + 1) * NH];      // folded input term (b0 included), padded 1 row
__device__ __align__(16) float g_W0T4[155 * NH * 4];    // Wh0_x transposed, float4-per-k4 layout
__device__ __align__(16) float g_M[NH * NH];            // Wh0_s @ Wh2
__device__ __align__(16) float g_P[256 * NH];           // Wc0 @ Wh2
__device__ float g_d[NH];                               // Wh0_s @ b2
__device__ float g_e[256];                              // Wc0 @ b2 + bc0

// ---------------- packed fp32x2 helpers (Blackwell FFMA2) --------------------
__device__ __forceinline__ unsigned long long ffma2(unsigned long long a,
                                                    unsigned long long b,
                                                    unsigned long long c) {
    unsigned long long d;
    asm("fma.rn.f32x2 %0, %1, %2, %3;" : "=l"(d) : "l"(a), "l"(b), "l"(c));
    return d;
}
__device__ __forceinline__ float sum2(unsigned long long v) {
    float x, y;
    asm("mov.b64 {%0, %1}, %2;" : "=f"(x), "=f"(y) : "l"(v));
    return x + y;
}

// ---------------- kernel A0: transpose Wh0_x into [k4][i][4] -----------------
__global__ void k_transpose(const float* __restrict__ Wh0) {
    int k = blockIdx.x;       // 0..619
    int i = threadIdx.x;      // 0..127
    g_W0T4[((k >> 2) * NH + i) * 4 + (k & 3)] = Wh0[i * NIN + k];
}

// ---------------- kernel A: U[t][i] = b0[i] + Wh0_x[i,:] . fvs[t,:] ----------
// grid 2048 blocks, 128 threads; each block does 8 timesteps
__global__ void k_ugemm(const float* __restrict__ fvs, const float* __restrict__ b0) {
    __shared__ __align__(16) float xsh[8 * FEAT];
    const int i  = threadIdx.x;
    const int t0 = blockIdx.x * 8;
    // fvs rows are contiguous: [t0*620 .. t0*620 + 8*620)
    for (int idx = i; idx < 8 * FEAT; idx += 128)
        xsh[idx] = fvs[t0 * FEAT + idx];
    __syncthreads();

    float b = b0[i];
    float acc[8] = {b, b, b, b, b, b, b, b};
    const float4* W4 = reinterpret_cast<const float4*>(g_W0T4);
    #pragma unroll 5
    for (int k4 = 0; k4 < 155; k4++) {
        float4 w = W4[k4 * NH + i];
        #pragma unroll
        for (int r = 0; r < 8; r++) {
            float4 x = *reinterpret_cast<const float4*>(&xsh[r * FEAT + 4 * k4]);
            acc[r] = fmaf(w.x, x.x, fmaf(w.y, x.y, fmaf(w.z, x.z, fmaf(w.w, x.w, acc[r]))));
        }
    }
    #pragma unroll
    for (int r = 0; r < 8; r++)
        g_U[(t0 + r) * NH + i] = acc[r];
}

// ---------------- kernel B: fold M = Wh0_s@Wh2 and P = Wc0@Wh2 ---------------
// grid 384 blocks (128 for M rows, 256 for P rows), 128 threads (j)
__global__ void k_fold(const float* __restrict__ Wh0,
                       const float* __restrict__ Wh2,
                       const float* __restrict__ Wc0) {
    __shared__ float Lsh[128];
    const int b = blockIdx.x;
    const int j = threadIdx.x;
    const float* Lrow = (b < 128) ? (Wh0 + b * NIN + FEAT)
                                  : (Wc0 + (b - 128) * STATE);
    float acc = 0.0f;
    for (int s0 = 0; s0 < STATE; s0 += 128) {
        Lsh[j] = Lrow[s0 + j];
        __syncthreads();
        #pragma unroll 8
        for (int s = 0; s < 128; s++)
            acc = fmaf(Lsh[s], Wh2[(s0 + s) * NH + j], acc);
        __syncthreads();
    }
    if (b < 128) g_M[b * NH + j] = acc;
    else         g_P[(b - 128) * NH + j] = acc;
}

// ---------------- kernel pd: d = Wh0_s@b2, e = Wc0@b2 + bc0 ------------------
__global__ void k_pd(const float* __restrict__ Wh0, const float* __restrict__ b2,
                     const float* __restrict__ Wc0, const float* __restrict__ bc0) {
    __shared__ float bsh[STATE];
    const int tid = threadIdx.x;   // 0..383
    for (int s = tid; s < STATE; s += 384) bsh[s] = b2[s];
    __syncthreads();
    if (tid < 128) {
        const float* row = Wh0 + tid * NIN + FEAT;
        float a = 0.0f;
        #pragma unroll 8
        for (int s = 0; s < STATE; s++) a = fmaf(row[s], bsh[s], a);
        g_d[tid] = a;
    } else {
        const int j = tid - 128;
        const float* row = Wc0 + j * STATE;
        float a = bc0[j];
        #pragma unroll 8
        for (int s = 0; s < STATE; s++) a = fmaf(row[s], bsh[s], a);
        g_e[j] = a;
    }
}

// ---------------- kernel C: the sequential scan (persistent single CTA) ------
// 256 threads. Warps 0-3 hold M rows in registers (phase 1), warps 4-7 hold
// Wh1 rows (phase 2). Two barriers per step. U prefetched one step ahead.
__global__ __launch_bounds__(256, 1)
void k_seq(const float* __restrict__ Wh1, const float* __restrict__ b1,
           const float* __restrict__ Wc1, const float* __restrict__ bc1,
           const int* __restrict__ marginp, float* __restrict__ out) {
    __shared__ __align__(16) float ysh[NH];    // y2 (current carried activation)
    __shared__ __align__(16) float y1sh[NH];   // y1 (inner activation)
    __shared__ float rsh[256];

    const int  tid = threadIdx.x;
    const bool g1  = tid < 128;

    // load this thread's 128 weights (64 packed f32x2)
    const unsigned long long* wsrc =
        g1 ? reinterpret_cast<const unsigned long long*>(g_M) + tid * 64
           : reinterpret_cast<const unsigned long long*>(Wh1) + (tid - 128) * 64;
    unsigned long long w[64];
    #pragma unroll
    for (int k = 0; k < 64; k++) w[k] = wsrc[k];

    const float bias = g1 ? g_d[tid] : b1[tid - 128];
    float u = g1 ? g_U[tid] : 0.0f;            // prefetch for t=0
    if (g1) ysh[tid] = 0.0f;                   // state0 = 0 => y2_{-1} := 0
    __syncthreads();

    const float marginf = (float)(*marginp);

    for (int t = 0; t < TT; t++) {
        if (g1) {
            // phase 1: y1 = relu(u_t + M @ y2 + d*(t>0))
            const ulonglong2* yv = reinterpret_cast<const ulonglong2*>(ysh);
            unsigned long long a0 = 0ull, a1 = 0ull, a2 = 0ull, a3 = 0ull;
            #pragma unroll
            for (int k = 0; k < 32; k += 2) {
                ulonglong2 p = yv[k];
                a0 = ffma2(w[2 * k + 0], p.x, a0);
                a1 = ffma2(w[2 * k + 1], p.y, a1);
                ulonglong2 q = yv[k + 1];
                a2 = ffma2(w[2 * k + 2], q.x, a2);
                a3 = ffma2(w[2 * k + 3], q.y, a3);
            }
            float s = sum2(a0) + sum2(a1) + sum2(a2) + sum2(a3);
            float val = u + s + (t ? bias : 0.0f);
            y1sh[tid] = fmaxf(val, 0.0f);
            u = g_U[(t + 1) * NH + tid];       // prefetch next step (padded row at t=TT-1)
        }
        __syncthreads();
        if (!g1) {
            // phase 2: y2 = relu(Wh1 @ y1 + b1)
            const ulonglong2* yv = reinterpret_cast<const ulonglong2*>(y1sh);
            unsigned long long a0 = 0ull, a1 = 0ull, a2 = 0ull, a3 = 0ull;
            #pragma unroll
            for (int k = 0; k < 32; k += 2) {
                ulonglong2 p = yv[k];
                a0 = ffma2(w[2 * k + 0], p.x, a0);
                a1 = ffma2(w[2 * k + 1], p.y, a1);
                ulonglong2 q = yv[k + 1];
                a2 = ffma2(w[2 * k + 2], q.x, a2);
                a3 = ffma2(w[2 * k + 3], q.y, a3);
            }
            float val = sum2(a0) + sum2(a1) + sum2(a2) + sum2(a3) + bias;
            ysh[tid - 128] = fmaxf(val, 0.0f);
        }
        __syncthreads();

        if ((t & 2047) == 2047) {
            // readout for sequence t>>11: out = tanh(Wc1 @ relu(P@y2 + e) + bc1)*margin
            float rj = g_e[tid];
            const float* Pr = g_P + tid * NH;
            #pragma unroll 8
            for (int k = 0; k < NH; k++) rj = fmaf(Pr[k], ysh[k], rj);
            rsh[tid] = fmaxf(rj, 0.0f);
            __syncthreads();
            if (tid < 2) {
                float o = bc1[tid];
                #pragma unroll 8
                for (int j = 0; j < 256; j++) o = fmaf(Wc1[tid * 256 + j], rsh[j], o);
                out[(t >> 11) * 2 + tid] = tanhf(o) * marginf;
            }
            __syncthreads();
        }
    }
}

// -----------------------------------------------------------------------------
extern "C" void kernel_launch(void* const* d_in, const int* in_sizes, int n_in,
                              void* d_out, int out_size) {
    const float* fvs  = (const float*)d_in[0];
    const float* Wh0  = (const float*)d_in[1];
    const float* bh0  = (const float*)d_in[2];
    const float* Wh1  = (const float*)d_in[3];
    const float* bh1  = (const float*)d_in[4];
    const float* Wh2  = (const float*)d_in[5];
    const float* bh2  = (const float*)d_in[6];
    const float* Wc0  = (const float*)d_in[7];
    const float* bc0  = (const float*)d_in[8];
    const float* Wc1  = (const float*)d_in[9];
    const float* bc1  = (const float*)d_in[10];
    const int*   marg = (const int*)d_in[11];
    float* out = (float*)d_out;

    k_transpose<<<620, 128>>>(Wh0);
    k_fold<<<384, 128>>>(Wh0, Wh2, Wc0);
    k_pd<<<1, 384>>>(Wh0, bh2, Wc0, bc0);
    k_ugemm<<<2048, 128>>>(fvs, bh0);
    k_seq<<<1, 256>>>(Wh1, bh1, Wc1, bc1, marg, out);
}